// round 13
// baseline (speedup 1.0000x reference)
#include <cuda_runtime.h>
#include <math.h>

// ---------------------------------------------------------------------------
// AddTaskModel SNN scan: S=1024, B=2048, D=2, H=128.
// Persistent batch-partitioned kernel: 128 CTAs x 256 threads, 16 batch/CTA.
// Each thread owns (1 hidden unit h, 8 batch elements).
//
// R12: packed fp32x2 (FFMA2) across the BATCH dimension.
//   - each fma.rn.f32x2 = two independent IEEE fp32 RN FMAs -> bit-identical
//     numerics to the passing R11 kernel (same ascending-K, single
//     accumulator per batch, bias after sum, expf sigmoid, double loss).
//   - state/activation arrays transposed to [j][16 batches] so a batch-pair
//     is one aligned LDS.64 feeding FFMA2 directly.
//   - streamed weights pre-replicated {w,w} in device scratch (LDG.64).
// ---------------------------------------------------------------------------

#define H        128
#define BT       16          // batch per CTA
#define NCTA     128
#define NTHREADS 256
#define NSTEPS   1024
#define BTOT     2048

// Shared layout (floats) — transposed state arrays [j][16], same sizes
#define OFF_WMD   0            // 16384  WtauM dense-half, [j][h]
#define OFF_WAD   16384        // 16384  WtauAdp dense-half, [j][h]
#define OFF_WMM   32768        // 16384  WtauM mem-half, [j][h]
#define OFF_DEN   49152        // 2048   dense[j][16]   (readout reuses as [b][h])
#define OFF_MEM   51200        // 2048   mem[j][16]
#define OFF_BB    53248        // 2048   bb[j][16]
#define OFF_SPK   55296        // 2048   spk[j][16]
#define OFF_BTM   57344        // 128
#define OFF_BTA   57472        // 128
#define OFF_B1X   57600        // 128
#define OFF_W1XX  57728        // 256    W1x x-part, [d][h]
#define OFF_XT    57984        // 32     x_t; reused as double[16] for loss
#define SMEM_FLOATS 58016
#define SMEM_BYTES  (SMEM_FLOATS * 4)   // 232064 <= 232448

typedef unsigned long long u64;

// __device__ scratch
__device__ float  gWmD[128 * 128];
__device__ float  gWaD[128 * 128];
__device__ float  gWmM[128 * 128];
__device__ u64    gW1xS2[128 * 128];  // streamed W1x spk-part, replicated {w,w}, [j][h]
__device__ u64    gWaB2[128 * 128];   // streamed WtauAdp bb-half, replicated {w,w}, [j][h]
__device__ float  gW1xX[2 * 128];     // W1x x-part, [d][h]
__device__ double gDloss;

__device__ __forceinline__ u64 pack2(float lo, float hi)
{
    u64 r;
    asm("mov.b64 %0, {%1, %2};" : "=l"(r) : "r"(__float_as_uint(lo)), "r"(__float_as_uint(hi)));
    return r;
}

__device__ __forceinline__ void unpack2(u64 v, float& lo, float& hi)
{
    unsigned int l, h_;
    asm("mov.b64 {%0, %1}, %2;" : "=r"(l), "=r"(h_) : "l"(v));
    lo = __uint_as_float(l);
    hi = __uint_as_float(h_);
}

// packed fp32x2 FMA: acc.lo += a.lo*b.lo ; acc.hi += a.hi*b.hi  (both IEEE RN)
__device__ __forceinline__ void ffma2(u64& acc, u64 a, u64 b)
{
    asm("fma.rn.f32x2 %0, %1, %2, %0;" : "+l"(acc) : "l"(a), "l"(b));
}

__global__ void prep_kernel(const float* __restrict__ W1x,
                            const float* __restrict__ WtauM,
                            const float* __restrict__ WtauAdp)
{
    int j = blockIdx.x;      // 0..127
    int h = threadIdx.x;     // 0..127
    gWmD[j * 128 + h] = WtauM[h * 256 + j];
    gWmM[j * 128 + h] = WtauM[h * 256 + 128 + j];
    gWaD[j * 128 + h] = WtauAdp[h * 256 + j];
    {
        float w = WtauAdp[h * 256 + 128 + j];
        gWaB2[j * 128 + h] = pack2(w, w);
    }
    {
        float w = W1x[h * 130 + 2 + j];
        gW1xS2[j * 128 + h] = pack2(w, w);
    }
    if (j < 2) gW1xX[j * 128 + h] = W1x[h * 130 + j];
    if (j == 0 && h == 0) gDloss = 0.0;   // graph replays: re-zero every launch
}

__global__ void finalize_kernel(float* __restrict__ out)
{
    out[0] = (float)(gDloss * (1.0 / 2048.0));
}

// XLA logistic (exp form): sigmoid(x) = 1 / (1 + exp(-x)), libm expf, IEEE div
__device__ __forceinline__ float sigmoid_ref(float v)
{
    return 1.0f / (1.0f + expf(-v));
}

__global__ __launch_bounds__(NTHREADS, 1)
void snn_kernel(const float* __restrict__ x,      // [S,B,D]
                const float* __restrict__ y,      // [B]
                const float* __restrict__ h0m,
                const float* __restrict__ h0s,
                const float* __restrict__ h0b,
                const float* __restrict__ b1x,
                const float* __restrict__ btm,
                const float* __restrict__ bta,
                const float* __restrict__ Wlin,   // [H]
                const float* __restrict__ blin)   // [1]
{
    extern __shared__ float sm[];
    float* sWmD = sm + OFF_WMD;
    float* sWaD = sm + OFF_WAD;
    float* sWmM = sm + OFF_WMM;
    float* sDen = sm + OFF_DEN;   // [j][16] during scan, [b][h] at readout
    float* sMem = sm + OFF_MEM;   // [j][16]
    float* sBb  = sm + OFF_BB;    // [j][16]
    float* sSpk = sm + OFF_SPK;   // [j][16]
    float* sBtm = sm + OFF_BTM;
    float* sBta = sm + OFF_BTA;
    float* sB1x = sm + OFF_B1X;
    float* sW1xX = sm + OFF_W1XX;
    float* sXt  = sm + OFF_XT;

    const int tid    = threadIdx.x;
    const int batch0 = blockIdx.x * BT;

    const int w      = tid >> 5;
    const int lane   = tid & 31;
    const int hblock = (w & 3) * 32;
    const int h      = hblock + lane;
    const int bg     = (w >> 2) * 8;      // batch group base (0 or 8)

    // ---- one-time loads ----
    for (int i = tid; i < 16384; i += NTHREADS) {
        sWmD[i] = gWmD[i];
        sWaD[i] = gWaD[i];
        sWmM[i] = gWmM[i];
    }
    if (tid < 128) {
        sBtm[tid] = btm[tid];
        sBta[tid] = bta[tid];
        sB1x[tid] = b1x[tid];
    }
    sW1xX[tid] = gW1xX[tid];

    // ---- state in registers; transposed shared copies for GEMM inputs ----
    float mem_r[8], bb_r[8], spk_r[8];
    #pragma unroll
    for (int b = 0; b < 8; ++b) {
        const int gidx = (batch0 + bg + b) * H + h;
        const int idx  = h * BT + bg + b;          // transposed [j=h][b]
        mem_r[b] = h0m[gidx];
        spk_r[b] = h0s[gidx];
        bb_r[b]  = h0b[gidx];
        sMem[idx] = mem_r[b];
        sSpk[idx] = spk_r[b];
        sBb[idx]  = bb_r[b];
    }
    __syncthreads();

    const u64* gs2 = gW1xS2 + h;          // stride 128 per j
    const u64* ga2 = gWaB2 + h;

    for (int t = 0; t < NSTEPS; ++t) {
        // stage x_t for this CTA's 16 batches (32 floats, contiguous)
        if (tid < 32) sXt[tid] = x[((size_t)t * BTOT + batch0) * 2 + tid];
        __syncthreads();   // also orders previous step's phase-3 shared writes

        // -------- phase 1: dense = [x_t, spk] @ W1x.T ; + b1x after --------
        // per-batch single fp32 accumulator, ascending K; batches paired 2/reg
        float d[8];
        const float w1x0 = sW1xX[h];
        const float w1x1 = sW1xX[128 + h];
        #pragma unroll
        for (int b = 0; b < 8; ++b) {
            const int bl = bg + b;
            d[b] = fmaf(w1x1, sXt[bl * 2 + 1], w1x0 * sXt[bl * 2]);
        }
        u64 d2[4];
        #pragma unroll
        for (int p = 0; p < 4; ++p) d2[p] = pack2(d[2 * p], d[2 * p + 1]);
        {
            u64 wn[8];
            #pragma unroll
            for (int k = 0; k < 8; ++k) wn[k] = __ldg(gs2 + k * 128);
            for (int j0 = 0; j0 < 128; j0 += 8) {
                u64 wc[8];
                #pragma unroll
                for (int k = 0; k < 8; ++k) wc[k] = wn[k];
                if (j0 + 8 < 128) {
                    #pragma unroll
                    for (int k = 0; k < 8; ++k) wn[k] = __ldg(gs2 + (j0 + 8 + k) * 128);
                }
                #pragma unroll
                for (int k = 0; k < 8; ++k) {
                    const u64* sp = (const u64*)(sSpk + (j0 + k) * BT + bg);
                    #pragma unroll
                    for (int p = 0; p < 4; ++p) ffma2(d2[p], sp[p], wc[k]);
                }
            }
        }
        const float bias1 = sB1x[h];
        #pragma unroll
        for (int p = 0; p < 4; ++p) unpack2(d2[p], d[2 * p], d[2 * p + 1]);
        #pragma unroll
        for (int b = 0; b < 8; ++b) d[b] = d[b] + bias1;   // bias AFTER the sum
        {
            float4 v0 = make_float4(d[0], d[1], d[2], d[3]);
            float4 v1 = make_float4(d[4], d[5], d[6], d[7]);
            *(float4*)(sDen + h * BT + bg)     = v0;
            *(float4*)(sDen + h * BT + bg + 4) = v1;
        }
        __syncthreads();

        // -------- phase 2: tau pre-activations (K=256, ascending) --------
        u64 accM2[4], accA2[4];
        #pragma unroll
        for (int p = 0; p < 4; ++p) { accM2[p] = 0ULL; accA2[p] = 0ULL; }

        // dense-input half (shared by both matrices), j = 0..127
        for (int j0 = 0; j0 < 128; j0 += 8) {
            u64 wmp[8], wap[8];
            #pragma unroll
            for (int k = 0; k < 8; ++k) {
                const float wm = sWmD[(j0 + k) * 128 + h];
                const float wa = sWaD[(j0 + k) * 128 + h];
                wmp[k] = pack2(wm, wm);
                wap[k] = pack2(wa, wa);
            }
            #pragma unroll
            for (int k = 0; k < 8; ++k) {
                const u64* dp = (const u64*)(sDen + (j0 + k) * BT + bg);
                #pragma unroll
                for (int p = 0; p < 4; ++p) {
                    const u64 dv = dp[p];
                    ffma2(accM2[p], dv, wmp[k]);
                    ffma2(accA2[p], dv, wap[k]);
                }
            }
        }
        // tauM mem-half, j = 128..255 (same accumulator, ascending)
        for (int j0 = 0; j0 < 128; j0 += 8) {
            u64 wmp[8];
            #pragma unroll
            for (int k = 0; k < 8; ++k) {
                const float wm = sWmM[(j0 + k) * 128 + h];
                wmp[k] = pack2(wm, wm);
            }
            #pragma unroll
            for (int k = 0; k < 8; ++k) {
                const u64* mp = (const u64*)(sMem + (j0 + k) * BT + bg);
                #pragma unroll
                for (int p = 0; p < 4; ++p) ffma2(accM2[p], mp[p], wmp[k]);
            }
        }
        // tauA bb-half, j = 128..255 (streamed replicated weights, prefetched)
        {
            u64 wn[8];
            #pragma unroll
            for (int k = 0; k < 8; ++k) wn[k] = __ldg(ga2 + k * 128);
            for (int j0 = 0; j0 < 128; j0 += 8) {
                u64 wc[8];
                #pragma unroll
                for (int k = 0; k < 8; ++k) wc[k] = wn[k];
                if (j0 + 8 < 128) {
                    #pragma unroll
                    for (int k = 0; k < 8; ++k) wn[k] = __ldg(ga2 + (j0 + 8 + k) * 128);
                }
                #pragma unroll
                for (int k = 0; k < 8; ++k) {
                    const u64* bp = (const u64*)(sBb + (j0 + k) * BT + bg);
                    #pragma unroll
                    for (int p = 0; p < 4; ++p) ffma2(accA2[p], bp[p], wc[k]);
                }
            }
        }
        __syncthreads();   // everyone done READING old state copies

        // -------- phase 3: elementwise state update (identical scalar ops) --
        float accM[8], accA[8];
        #pragma unroll
        for (int p = 0; p < 4; ++p) {
            unpack2(accM2[p], accM[2 * p], accM[2 * p + 1]);
            unpack2(accA2[p], accA[2 * p], accA[2 * p + 1]);
        }
        const float bm = sBtm[h], ba = sBta[h];
        float bnv[8], mnv[8], snv[8];
        #pragma unroll
        for (int b = 0; b < 8; ++b) {
            const float tm = sigmoid_ref(accM[b] + bm);
            const float ta = sigmoid_ref(accA[b] + ba);
            const float spo = spk_r[b];
            const float bn  = ta * bb_r[b] + (1.0f - ta) * spo;
            const float Bth = 0.01f + 1.8f * bn;
            const float mn  = mem_r[b] * tm + (1.0f - tm) * d[b] - Bth * spo;
            const float sn  = (mn - Bth > 0.0f) ? 1.0f : 0.0f;
            bb_r[b]  = bn;
            mem_r[b] = mn;
            spk_r[b] = sn;
            bnv[b] = bn; mnv[b] = mn; snv[b] = sn;
        }
        *(float4*)(sBb  + h * BT + bg)     = make_float4(bnv[0], bnv[1], bnv[2], bnv[3]);
        *(float4*)(sBb  + h * BT + bg + 4) = make_float4(bnv[4], bnv[5], bnv[6], bnv[7]);
        *(float4*)(sMem + h * BT + bg)     = make_float4(mnv[0], mnv[1], mnv[2], mnv[3]);
        *(float4*)(sMem + h * BT + bg + 4) = make_float4(mnv[4], mnv[5], mnv[6], mnv[7]);
        *(float4*)(sSpk + h * BT + bg)     = make_float4(snv[0], snv[1], snv[2], snv[3]);
        *(float4*)(sSpk + h * BT + bg + 4) = make_float4(snv[4], snv[5], snv[6], snv[7]);
    }
    __syncthreads();

    // -------- readout: out[b] = mem[b] @ Wlin + blin -------
    // park true mem in sDen region as [b][h]
    #pragma unroll
    for (int b = 0; b < 8; ++b) sDen[(bg + b) * H + h] = mem_r[b];
    __syncthreads();

    double* sD = (double*)sXt;   // 16 doubles, 8B aligned
    #pragma unroll
    for (int r = 0; r < 2; ++r) {
        const int bl = w * 2 + r;
        double p = 0.0;
        #pragma unroll
        for (int o = 0; o < 4; ++o) {
            const int hh = lane + 32 * o;
            p += (double)sDen[bl * H + hh] * (double)Wlin[hh];
        }
        #pragma unroll
        for (int off = 16; off; off >>= 1) p += __shfl_xor_sync(0xFFFFFFFFu, p, off);
        if (lane == 0) {
            const double o  = p + (double)blin[0];
            const double df = o - (double)y[batch0 + bl];
            sD[bl] = df * df;
        }
    }
    __syncthreads();
    if (tid == 0) {
        double s = 0.0;
        #pragma unroll
        for (int i = 0; i < BT; ++i) s += sD[i];
        atomicAdd(&gDloss, s);
    }
}

extern "C" void kernel_launch(void* const* d_in, const int* in_sizes, int n_in,
                              void* d_out, int out_size)
{
    const float* x       = (const float*)d_in[0];
    const float* y       = (const float*)d_in[1];
    const float* h0_mem  = (const float*)d_in[2];
    const float* h0_spk  = (const float*)d_in[3];
    const float* h0_b    = (const float*)d_in[4];
    const float* W1x     = (const float*)d_in[5];
    const float* b1x     = (const float*)d_in[6];
    const float* WtauM   = (const float*)d_in[7];
    const float* btauM   = (const float*)d_in[8];
    const float* WtauAdp = (const float*)d_in[9];
    const float* btauAdp = (const float*)d_in[10];
    const float* Wlin    = (const float*)d_in[11];
    const float* blin    = (const float*)d_in[12];
    float* out = (float*)d_out;

    cudaFuncSetAttribute(snn_kernel, cudaFuncAttributeMaxDynamicSharedMemorySize,
                         SMEM_BYTES);

    prep_kernel<<<128, 128>>>(W1x, WtauM, WtauAdp);
    snn_kernel<<<NCTA, NTHREADS, SMEM_BYTES>>>(x, y, h0_mem, h0_spk, h0_b,
                                               b1x, btauM, btauAdp,
                                               Wlin, blin);
    finalize_kernel<<<1, 1>>>(out);
}

// round 15
// speedup vs baseline: 1.5399x; 1.5399x over previous
#include <cuda_runtime.h>
#include <math.h>

// ---------------------------------------------------------------------------
// AddTaskModel SNN scan: S=1024, B=2048, D=2, H=128.
// Persistent batch-partitioned kernel: 128 CTAs x 256 threads, 16 batch/CTA.
// Each thread owns (1 hidden unit h, 8 batch elements).
//
// R13 = R11 (passing, 15.7ms, rel_err 9e-8) with finalize folded into the
// main kernel (last-CTA pattern, fixed-order deterministic double sum).
// 2 launches/call -> ncu -s 5 -c 1 now captures snn_kernel, not prep.
// Arithmetic is UNTOUCHED (bit-identical trajectory to R11):
//   - ascending-K single-fp32-accumulator FMA dots (cublas order)
//   - bias after sum, sigmoid = 1/(1+expf(-x)) IEEE divide
//   - fp32 register state, double-precision loss
// ---------------------------------------------------------------------------

#define H        128
#define BT       16          // batch per CTA
#define NCTA     128
#define NTHREADS 256
#define NSTEPS   1024
#define BTOT     2048

// Shared layout (floats)
#define OFF_WMD   0            // 16384  WtauM dense-half, [j][h]
#define OFF_WAD   16384        // 16384  WtauAdp dense-half, [j][h]
#define OFF_WMM   32768        // 16384  WtauM mem-half, [j][h]
#define OFF_DEN   49152        // 2048   dense[b][j]
#define OFF_MEM   51200        // 2048   mem
#define OFF_BB    53248        // 2048   bb
#define OFF_SPK   55296        // 2048   spk (0/1)
#define OFF_BTM   57344        // 128
#define OFF_BTA   57472        // 128
#define OFF_B1X   57600        // 128
#define OFF_W1XX  57728        // 256    W1x x-part, [d][h]
#define OFF_XT    57984        // 32     x_t; reused as double[16] for loss
#define SMEM_FLOATS 58016
#define SMEM_BYTES  (SMEM_FLOATS * 4)   // 232064 <= 232448

// __device__ scratch (static device globals are allowed)
__device__ float        gWmD[128 * 128];
__device__ float        gWaD[128 * 128];
__device__ float        gWmM[128 * 128];
__device__ float        gWaB[128 * 128];   // streamed: WtauAdp bb-half, [j][h]
__device__ float        gW1xS[128 * 128];  // streamed: W1x spk-part, [j][h]
__device__ float        gW1xX[2 * 128];    // W1x x-part, [d][h]
__device__ double       gPart[NCTA];       // per-CTA loss partials
__device__ unsigned int gDone;             // completion counter (0 at rest)

__global__ void prep_kernel(const float* __restrict__ W1x,
                            const float* __restrict__ WtauM,
                            const float* __restrict__ WtauAdp)
{
    int j = blockIdx.x;      // 0..127
    int h = threadIdx.x;     // 0..127
    gWmD[j * 128 + h]  = WtauM[h * 256 + j];
    gWmM[j * 128 + h]  = WtauM[h * 256 + 128 + j];
    gWaD[j * 128 + h]  = WtauAdp[h * 256 + j];
    gWaB[j * 128 + h]  = WtauAdp[h * 256 + 128 + j];
    gW1xS[j * 128 + h] = W1x[h * 130 + 2 + j];
    if (j < 2) gW1xX[j * 128 + h] = W1x[h * 130 + j];
}

// XLA logistic (exp form): sigmoid(x) = 1 / (1 + exp(-x)), libm expf, IEEE div
__device__ __forceinline__ float sigmoid_ref(float v)
{
    return 1.0f / (1.0f + expf(-v));
}

__global__ __launch_bounds__(NTHREADS, 1)
void snn_kernel(const float* __restrict__ x,      // [S,B,D]
                const float* __restrict__ y,      // [B]
                const float* __restrict__ h0m,
                const float* __restrict__ h0s,
                const float* __restrict__ h0b,
                const float* __restrict__ b1x,
                const float* __restrict__ btm,
                const float* __restrict__ bta,
                const float* __restrict__ Wlin,   // [H]
                const float* __restrict__ blin,   // [1]
                float* __restrict__ out)
{
    extern __shared__ float sm[];
    float* sWmD = sm + OFF_WMD;
    float* sWaD = sm + OFF_WAD;
    float* sWmM = sm + OFF_WMM;
    float* sDen = sm + OFF_DEN;
    float* sMem = sm + OFF_MEM;
    float* sBb  = sm + OFF_BB;
    float* sSpk = sm + OFF_SPK;
    float* sBtm = sm + OFF_BTM;
    float* sBta = sm + OFF_BTA;
    float* sB1x = sm + OFF_B1X;
    float* sW1xX = sm + OFF_W1XX;
    float* sXt  = sm + OFF_XT;

    const int tid    = threadIdx.x;
    const int batch0 = blockIdx.x * BT;

    const int w      = tid >> 5;
    const int lane   = tid & 31;
    const int hblock = (w & 3) * 32;
    const int h      = hblock + lane;
    const int bg     = (w >> 2) * 8;      // batch group base (0 or 8)

    // ---- one-time loads ----
    for (int i = tid; i < 16384; i += NTHREADS) {
        sWmD[i] = gWmD[i];
        sWaD[i] = gWaD[i];
        sWmM[i] = gWmM[i];
    }
    if (tid < 128) {
        sBtm[tid] = btm[tid];
        sBta[tid] = bta[tid];
        sB1x[tid] = b1x[tid];
    }
    sW1xX[tid] = gW1xX[tid];   // 256 values, 256 threads

    // ---- state in registers; shared holds copies used as GEMM inputs ----
    float mem_r[8], bb_r[8], spk_r[8];
    #pragma unroll
    for (int b = 0; b < 8; ++b) {
        const int gidx = (batch0 + bg + b) * H + h;
        const int idx  = (bg + b) * H + h;
        mem_r[b] = h0m[gidx];
        spk_r[b] = h0s[gidx];
        bb_r[b]  = h0b[gidx];
        sMem[idx] = mem_r[b];
        sSpk[idx] = spk_r[b];
        sBb[idx]  = bb_r[b];
    }
    __syncthreads();

    const float* gs = gW1xS + h;          // stride 128 per j
    const float* ga = gWaB + h;

    for (int t = 0; t < NSTEPS; ++t) {
        // stage x_t for this CTA's 16 batches (32 floats, contiguous)
        if (tid < 32) sXt[tid] = x[((size_t)t * BTOT + batch0) * 2 + tid];
        __syncthreads();   // also orders previous step's phase-3 shared writes

        // -------- phase 1: dense = [x_t, spk] @ W1x.T ; + b1x after --------
        // single fp32 accumulator, ascending K = [x0, x1, spk0..spk127]
        float d[8];
        const float w1x0 = sW1xX[h];
        const float w1x1 = sW1xX[128 + h];
        #pragma unroll
        for (int b = 0; b < 8; ++b) {
            const int bl = bg + b;
            d[b] = fmaf(w1x1, sXt[bl * 2 + 1], w1x0 * sXt[bl * 2]);
        }
        {
            float wn[8];
            #pragma unroll
            for (int k = 0; k < 8; ++k) wn[k] = __ldg(gs + k * 128);
            for (int j0 = 0; j0 < 128; j0 += 8) {
                float wc[8];
                #pragma unroll
                for (int k = 0; k < 8; ++k) wc[k] = wn[k];
                if (j0 + 8 < 128) {
                    #pragma unroll
                    for (int k = 0; k < 8; ++k) wn[k] = __ldg(gs + (j0 + 8 + k) * 128);
                }
                #pragma unroll
                for (int b = 0; b < 8; ++b) {
                    const float4 s0 = *(const float4*)(sSpk + (bg + b) * H + j0);
                    const float4 s1 = *(const float4*)(sSpk + (bg + b) * H + j0 + 4);
                    float a = d[b];
                    a = fmaf(s0.x, wc[0], a); a = fmaf(s0.y, wc[1], a);
                    a = fmaf(s0.z, wc[2], a); a = fmaf(s0.w, wc[3], a);
                    a = fmaf(s1.x, wc[4], a); a = fmaf(s1.y, wc[5], a);
                    a = fmaf(s1.z, wc[6], a); a = fmaf(s1.w, wc[7], a);
                    d[b] = a;
                }
            }
        }
        const float bias1 = sB1x[h];
        #pragma unroll
        for (int b = 0; b < 8; ++b) {
            d[b] = d[b] + bias1;                    // bias AFTER the sum
            sDen[(bg + b) * H + h] = d[b];
        }
        __syncthreads();

        // -------- phase 2: tau pre-activations (K=256, ascending) --------
        float accM[8], accA[8];
        #pragma unroll
        for (int b = 0; b < 8; ++b) { accM[b] = 0.0f; accA[b] = 0.0f; }

        // dense-input half (shared by both matrices), j = 0..127
        for (int j0 = 0; j0 < 128; j0 += 8) {
            float wm[8], wa[8];
            #pragma unroll
            for (int k = 0; k < 8; ++k) {
                wm[k] = sWmD[(j0 + k) * 128 + h];
                wa[k] = sWaD[(j0 + k) * 128 + h];
            }
            #pragma unroll
            for (int b = 0; b < 8; ++b) {
                const float4 d0 = *(const float4*)(sDen + (bg + b) * H + j0);
                const float4 d1 = *(const float4*)(sDen + (bg + b) * H + j0 + 4);
                float am = accM[b];
                am = fmaf(d0.x, wm[0], am); am = fmaf(d0.y, wm[1], am);
                am = fmaf(d0.z, wm[2], am); am = fmaf(d0.w, wm[3], am);
                am = fmaf(d1.x, wm[4], am); am = fmaf(d1.y, wm[5], am);
                am = fmaf(d1.z, wm[6], am); am = fmaf(d1.w, wm[7], am);
                accM[b] = am;
                float aa = accA[b];
                aa = fmaf(d0.x, wa[0], aa); aa = fmaf(d0.y, wa[1], aa);
                aa = fmaf(d0.z, wa[2], aa); aa = fmaf(d0.w, wa[3], aa);
                aa = fmaf(d1.x, wa[4], aa); aa = fmaf(d1.y, wa[5], aa);
                aa = fmaf(d1.z, wa[6], aa); aa = fmaf(d1.w, wa[7], aa);
                accA[b] = aa;
            }
        }
        // tauM mem-half, j = 128..255 (continues same accumulator, ascending)
        for (int j0 = 0; j0 < 128; j0 += 8) {
            float wm[8];
            #pragma unroll
            for (int k = 0; k < 8; ++k) wm[k] = sWmM[(j0 + k) * 128 + h];
            #pragma unroll
            for (int b = 0; b < 8; ++b) {
                const float4 m0 = *(const float4*)(sMem + (bg + b) * H + j0);
                const float4 m1 = *(const float4*)(sMem + (bg + b) * H + j0 + 4);
                float am = accM[b];
                am = fmaf(m0.x, wm[0], am); am = fmaf(m0.y, wm[1], am);
                am = fmaf(m0.z, wm[2], am); am = fmaf(m0.w, wm[3], am);
                am = fmaf(m1.x, wm[4], am); am = fmaf(m1.y, wm[5], am);
                am = fmaf(m1.z, wm[6], am); am = fmaf(m1.w, wm[7], am);
                accM[b] = am;
            }
        }
        // tauA bb-half, j = 128..255 (streamed weights, 8-deep prefetch)
        {
            float wn[8];
            #pragma unroll
            for (int k = 0; k < 8; ++k) wn[k] = __ldg(ga + k * 128);
            for (int j0 = 0; j0 < 128; j0 += 8) {
                float wc[8];
                #pragma unroll
                for (int k = 0; k < 8; ++k) wc[k] = wn[k];
                if (j0 + 8 < 128) {
                    #pragma unroll
                    for (int k = 0; k < 8; ++k) wn[k] = __ldg(ga + (j0 + 8 + k) * 128);
                }
                #pragma unroll
                for (int b = 0; b < 8; ++b) {
                    const float4 s0 = *(const float4*)(sBb + (bg + b) * H + j0);
                    const float4 s1 = *(const float4*)(sBb + (bg + b) * H + j0 + 4);
                    float aa = accA[b];
                    aa = fmaf(s0.x, wc[0], aa); aa = fmaf(s0.y, wc[1], aa);
                    aa = fmaf(s0.z, wc[2], aa); aa = fmaf(s0.w, wc[3], aa);
                    aa = fmaf(s1.x, wc[4], aa); aa = fmaf(s1.y, wc[5], aa);
                    aa = fmaf(s1.z, wc[6], aa); aa = fmaf(s1.w, wc[7], aa);
                    accA[b] = aa;
                }
            }
        }
        __syncthreads();   // everyone done READING old state copies

        // -------- phase 3: elementwise state update (plain fp32, RN) --------
        const float bm = sBtm[h], ba = sBta[h];
        #pragma unroll
        for (int b = 0; b < 8; ++b) {
            const int idx = (bg + b) * H + h;
            const float tm = sigmoid_ref(accM[b] + bm);
            const float ta = sigmoid_ref(accA[b] + ba);
            const float spo = spk_r[b];
            const float bn  = ta * bb_r[b] + (1.0f - ta) * spo;
            const float Bth = 0.01f + 1.8f * bn;
            const float mn  = mem_r[b] * tm + (1.0f - tm) * d[b] - Bth * spo;
            const float sn  = (mn - Bth > 0.0f) ? 1.0f : 0.0f;
            bb_r[b]  = bn;
            mem_r[b] = mn;
            spk_r[b] = sn;
            sBb[idx]  = bn;
            sMem[idx] = mn;
            sSpk[idx] = sn;
        }
    }
    __syncthreads();

    // -------- readout: out[b] = mem[b] @ Wlin + blin -------
    double* sD = (double*)sXt;   // 16 doubles, 8B aligned
    #pragma unroll
    for (int r = 0; r < 2; ++r) {
        const int bl = w * 2 + r;
        double p = 0.0;
        #pragma unroll
        for (int o = 0; o < 4; ++o) {
            const int hh = lane + 32 * o;
            p += (double)sMem[bl * H + hh] * (double)Wlin[hh];
        }
        #pragma unroll
        for (int off = 16; off; off >>= 1) p += __shfl_xor_sync(0xFFFFFFFFu, p, off);
        if (lane == 0) {
            const double o  = p + (double)blin[0];
            const double df = o - (double)y[batch0 + bl];
            sD[bl] = df * df;
        }
    }
    __syncthreads();

    // -------- folded finalize: last CTA reduces per-CTA partials --------
    if (tid == 0) {
        double s = 0.0;
        #pragma unroll
        for (int i = 0; i < BT; ++i) s += sD[i];
        gPart[blockIdx.x] = s;
        __threadfence();
        const unsigned int prev = atomicAdd(&gDone, 1u);
        if (prev == NCTA - 1) {
            // fixed-order sum over CTA index -> deterministic
            double tot = 0.0;
            for (int c = 0; c < NCTA; ++c) tot += gPart[c];
            out[0] = (float)(tot * (1.0 / 2048.0));
            gDone = 0;              // reset for the next (graph-replayed) call
            __threadfence();
        }
    }
}

extern "C" void kernel_launch(void* const* d_in, const int* in_sizes, int n_in,
                              void* d_out, int out_size)
{
    const float* x       = (const float*)d_in[0];
    const float* y       = (const float*)d_in[1];
    const float* h0_mem  = (const float*)d_in[2];
    const float* h0_spk  = (const float*)d_in[3];
    const float* h0_b    = (const float*)d_in[4];
    const float* W1x     = (const float*)d_in[5];
    const float* b1x     = (const float*)d_in[6];
    const float* WtauM   = (const float*)d_in[7];
    const float* btauM   = (const float*)d_in[8];
    const float* WtauAdp = (const float*)d_in[9];
    const float* btauAdp = (const float*)d_in[10];
    const float* Wlin    = (const float*)d_in[11];
    const float* blin    = (const float*)d_in[12];
    float* out = (float*)d_out;

    cudaFuncSetAttribute(snn_kernel, cudaFuncAttributeMaxDynamicSharedMemorySize,
                         SMEM_BYTES);

    prep_kernel<<<128, 128>>>(W1x, WtauM, WtauAdp);
    snn_kernel<<<NCTA, NTHREADS, SMEM_BYTES>>>(x, y, h0_mem, h0_spk, h0_b,
                                               b1x, btauM, btauAdp,
                                               Wlin, blin, out);
}